// round 4
// baseline (speedup 1.0000x reference)
#include <cuda_runtime.h>
#include <cuda_bf16.h>

// LSEP loss, factorized:
//   S_b = (sum_{neg} e^{x}) * (sum_{pos} e^{-x});  loss = mean_b log1p(S_b)
// N = 512 rows, C = 512 cols.
//
// Single kernel node (no memset). R1's fast body: one CTA per row, 128 threads,
// one float4 + one int4 per thread (16-reg footprint, max parallelism at
// grid=512). Cross-CTA combine via one float atomicAdd per CTA into a
// __device__ accumulator; the last-arriving CTA publishes the scalar with
// atomicExch (read + reset in one op, keeping the kernel replay-idempotent).

#define NROWS 512
#define NCOLS 512

__device__ float        g_accum;   // zero-initialized; reset by atomicExch each run
__device__ unsigned int g_count;   // zero-initialized; reset by last CTA each run

__global__ void __launch_bounds__(128) lsep_kernel(
    const int* __restrict__ y_true,
    const float* __restrict__ y_pred,
    float* __restrict__ out)
{
    const int row = blockIdx.x;
    const float4* __restrict__ pv = reinterpret_cast<const float4*>(y_pred + row * NCOLS);
    const int4*   __restrict__ tv = reinterpret_cast<const int4*>(y_true + row * NCOLS);

    // 512 cols = 128 float4 -> exactly one vector pair per thread
    const int i = threadIdx.x;
    float4 v = pv[i];
    int4   l = tv[i];

    float pos = 0.f, neg = 0.f;

#define ACC(LBL, VAL) do {                          \
        float e = __expf((LBL) ? -(VAL) : (VAL));   \
        if (LBL) pos += e; else neg += e;           \
    } while (0)

    ACC(l.x, v.x);
    ACC(l.y, v.y);
    ACC(l.z, v.z);
    ACC(l.w, v.w);
#undef ACC

    // warp reduction (two independent shuffle chains)
    #pragma unroll
    for (int off = 16; off > 0; off >>= 1) {
        pos += __shfl_xor_sync(0xFFFFFFFFu, pos, off);
        neg += __shfl_xor_sync(0xFFFFFFFFu, neg, off);
    }

    __shared__ float s_pos[4];
    __shared__ float s_neg[4];
    const int wid = threadIdx.x >> 5;
    const int lid = threadIdx.x & 31;
    if (lid == 0) { s_pos[wid] = pos; s_neg[wid] = neg; }
    __syncthreads();

    if (threadIdx.x == 0) {
        float p = s_pos[0] + s_pos[1] + s_pos[2] + s_pos[3];
        float n = s_neg[0] + s_neg[1] + s_neg[2] + s_neg[3];
        float contrib = log1pf(p * n);

        atomicAdd(&g_accum, contrib);
        __threadfence();                       // accum visible before counter bump
        unsigned int prev = atomicAdd(&g_count, 1u);
        if (prev == NROWS - 1) {
            // All 511 other CTAs have completed their g_accum add (fence-ordered
            // before their counter bump). Read total and reset in one atomic.
            float total = atomicExch(&g_accum, 0.0f);
            out[0] = total * (1.0f / (float)NROWS);
            g_count = 0;                       // reset for next graph replay
        }
    }
}

extern "C" void kernel_launch(void* const* d_in, const int* in_sizes, int n_in,
                              void* d_out, int out_size)
{
    const int*   y_true = (const int*)d_in[0];
    const float* y_pred = (const float*)d_in[1];
    float* out = (float*)d_out;

    lsep_kernel<<<NROWS, 128>>>(y_true, y_pred, out);
}